// round 14
// baseline (speedup 1.0000x reference)
#include <cuda_runtime.h>
#include <cuda_fp16.h>
#include <math_constants.h>
#include <cstdint>

// Problem constants
#define BATCH 2
#define SEQ   2048
#define CH    1024
#define HEADS 16
#define DH    64
#define MROWS (BATCH*SEQ)   // 4096

// ---------------------------------------------------------------------------
// Device scratch
// ---------------------------------------------------------------------------
__device__ float  g_qkv[(size_t)MROWS * 3 * CH];
__device__ __half g_A[(size_t)MROWS * CH];
__device__ __half g_BQ[(size_t)(3*CH) * CH];   // W_qkv^T fp16
__device__ __half g_BP[(size_t)CH * CH];       // W_proj^T fp16

// ---------------------------------------------------------------------------
// Helpers
// ---------------------------------------------------------------------------
__device__ __forceinline__ uint32_t smem_u32(const void* p) {
    uint32_t a;
    asm("{ .reg .u64 t; cvta.to.shared.u64 t, %1; cvt.u32.u64 %0, t; }"
        : "=r"(a) : "l"(p));
    return a;
}

#define SWZ128(o) ((o) ^ (((o) >> 3) & 0x70))

#define CP_ASYNC16(dst_u32, src_ptr) \
    asm volatile("cp.async.cg.shared.global [%0], [%1], 16;\n" \
                 :: "r"(dst_u32), "l"(src_ptr))
#define CP_COMMIT() asm volatile("cp.async.commit_group;\n" ::: "memory")
#define CP_WAIT0()  asm volatile("cp.async.wait_group 0;\n" ::: "memory")
#define CP_WAIT1()  asm volatile("cp.async.wait_group 1;\n" ::: "memory")

#define LDSM_X4(r0, r1, r2, r3, addr) \
    asm volatile("ldmatrix.sync.aligned.m8n8.x4.shared.b16 {%0,%1,%2,%3}, [%4];" \
                 : "=r"(r0), "=r"(r1), "=r"(r2), "=r"(r3) : "r"(addr))
// fp16 MMA, f32 accumulate
#define MMA16816(d, a0, a1, a2, a3, b0, b1) \
    asm volatile("mma.sync.aligned.m16n8k16.row.col.f32.f16.f16.f32 " \
                 "{%0,%1,%2,%3},{%4,%5,%6,%7},{%8,%9},{%0,%1,%2,%3};" \
                 : "+f"((d)[0]), "+f"((d)[1]), "+f"((d)[2]), "+f"((d)[3]) \
                 : "r"(a0), "r"(a1), "r"(a2), "r"(a3), "r"(b0), "r"(b1))

// ---------------------------------------------------------------------------
// fp16 GEMM: C[M,N] = A[M,K] @ B[N,K]^T + bias
// R11 EXACT (fastest measured): CTA 128x128, KC=64, 2-stage double buffer,
// TWO CTAs PER SM, 8 warps 2(M)x4(N), 64x32 warp tiles.
// ---------------------------------------------------------------------------
#define KC 64
#define STAGE_BYTES 32768
#define GEMM_SMEM (1024 + 2 * STAGE_BYTES)   // 66560 B

__device__ __forceinline__ void load_chunk_tiles(
    const __half* __restrict__ A, const __half* __restrict__ B,
    int K, int m0, int n0, int c, uint32_t st, int tid)
{
    #pragma unroll
    for (int t = 0; t < 4; t++) {
        int idx = t * 256 + tid;     // 0..1023
        int row = idx >> 3;          // 0..127
        int col = idx & 7;           // 16B chunk
        uint32_t off = SWZ128(row * 128 + col * 16);
        size_t ga = (size_t)(m0 + row) * K + c * KC + col * 8;
        size_t gb = (size_t)(n0 + row) * K + c * KC + col * 8;
        CP_ASYNC16(st + off,         A + ga);
        CP_ASYNC16(st + 16384 + off, B + gb);
    }
}

__global__ __launch_bounds__(256, 2)
void gemm_fp16_kernel(const __half* __restrict__ A,
                      const __half* __restrict__ B,
                      const float* __restrict__ bias,
                      float* __restrict__ C,
                      int N, int K)
{
    extern __shared__ char smem[];
    const uint32_t sb = smem_u32(smem);
    const uint32_t tiles = (sb + 1023) & ~1023u;
    const int tid  = threadIdx.x;
    const int wid  = tid >> 5;
    const int lane = tid & 31;
    const int m0 = blockIdx.y * 128;
    const int n0 = blockIdx.x * 128;
    const int NCHUNK = K / KC;

    const int warpM = wid >> 2;        // 0..1
    const int warpN = wid & 3;         // 0..3

    float acc[4][4][4];
    #pragma unroll
    for (int mt = 0; mt < 4; mt++)
        #pragma unroll
        for (int nt = 0; nt < 4; nt++)
            #pragma unroll
            for (int e = 0; e < 4; e++) acc[mt][nt][e] = 0.0f;

    // A ldmatrix.x4 (m16 x k16)
    const int aRowBase  = warpM * 64 + (lane & 15);
    const int aByteSel  = (lane >> 4) * 16;
    // B ldmatrix.x4 (two n8 tiles x k16) — layout verified R6-R13
    const int bRowSel   = warpN * 32 + (lane & 7) + ((lane >> 4) & 1) * 8;
    const int bByteSel  = ((lane >> 3) & 1) * 16;

    load_chunk_tiles(A, B, K, m0, n0, 0, tiles, tid);
    CP_COMMIT();

    for (int c = 0; c < NCHUNK; ++c) {
        if (c + 1 < NCHUNK) {
            load_chunk_tiles(A, B, K, m0, n0, c + 1,
                             tiles + ((c + 1) & 1) * STAGE_BYTES, tid);
            CP_COMMIT();
            CP_WAIT1();
        } else {
            CP_WAIT0();
        }
        __syncthreads();

        const uint32_t st = tiles + (c & 1) * STAGE_BYTES;
        const uint32_t aB = st;
        const uint32_t bB = st + 16384;

        #pragma unroll
        for (int kk = 0; kk < 4; kk++) {
            uint32_t fa[4][4], fb[2][4];
            #pragma unroll
            for (int mt = 0; mt < 4; mt++) {
                uint32_t aoff = SWZ128((uint32_t)((aRowBase + mt * 16) * 128 + kk * 32 + aByteSel));
                LDSM_X4(fa[mt][0], fa[mt][1], fa[mt][2], fa[mt][3], aB + aoff);
            }
            #pragma unroll
            for (int p = 0; p < 2; p++) {
                uint32_t boff = SWZ128((uint32_t)((bRowSel + p * 16) * 128 + kk * 32 + bByteSel));
                LDSM_X4(fb[p][0], fb[p][1], fb[p][2], fb[p][3], bB + boff);
            }
            #pragma unroll
            for (int mt = 0; mt < 4; mt++)
                #pragma unroll
                for (int nt = 0; nt < 4; nt++)
                    MMA16816(acc[mt][nt],
                             fa[mt][0], fa[mt][1], fa[mt][2], fa[mt][3],
                             fb[nt >> 1][(nt & 1) * 2], fb[nt >> 1][(nt & 1) * 2 + 1]);
        }
        __syncthreads();
    }

    // epilogue: bias + store
    #pragma unroll
    for (int mt = 0; mt < 4; mt++) {
        int r0 = m0 + warpM * 64 + mt * 16 + (lane >> 2);
        #pragma unroll
        for (int nt = 0; nt < 4; nt++) {
            int c0 = n0 + warpN * 32 + nt * 8 + (lane & 3) * 2;
            float2 bv = *(const float2*)(bias + c0);
            float2 o0 = make_float2(acc[mt][nt][0] + bv.x, acc[mt][nt][1] + bv.y);
            float2 o1 = make_float2(acc[mt][nt][2] + bv.x, acc[mt][nt][3] + bv.y);
            *(float2*)(C + (size_t)r0 * N + c0)       = o0;
            *(float2*)(C + (size_t)(r0 + 8) * N + c0) = o1;
        }
    }
}

// ---------------------------------------------------------------------------
// Convert fp32 -> fp16
// ---------------------------------------------------------------------------
__global__ __launch_bounds__(256)
void conv_fp16_kernel(const float* __restrict__ in,
                      __half* __restrict__ o, int n4)
{
    int i = blockIdx.x * 256 + threadIdx.x;
    if (i >= n4) return;
    float4 v = ((const float4*)in)[i];
    ((__half2*)o)[2 * i + 0] = __halves2half2(__float2half_rn(v.x), __float2half_rn(v.y));
    ((__half2*)o)[2 * i + 1] = __halves2half2(__float2half_rn(v.z), __float2half_rn(v.w));
}

// ---------------------------------------------------------------------------
// Transpose: W[K,N] fp32 -> Wt[N,K] fp16
// ---------------------------------------------------------------------------
__global__ __launch_bounds__(256)
void conv_transpose_kernel(const float* __restrict__ W,
                           __half* __restrict__ o, int K, int N)
{
    __shared__ float tile[32][33];
    const int n0 = blockIdx.x * 32;
    const int k0 = blockIdx.y * 32;
    const int tx = threadIdx.x & 31;
    const int ty = threadIdx.x >> 5;

    #pragma unroll
    for (int j = ty; j < 32; j += 8)
        tile[j][tx] = W[(size_t)(k0 + j) * N + n0 + tx];
    __syncthreads();

    #pragma unroll
    for (int j = ty; j < 32; j += 8)
        o[(size_t)(n0 + j) * K + k0 + tx] = __float2half_rn(tile[tx][j]);
}

// ---------------------------------------------------------------------------
// Fenwick sparse attention with near-window smem tiling.
// Block = (b, h, 64 consecutive queries). K,V rows [t0-64, t0+64) staged in
// smem (padded stride 68 floats). Near positions (diag + steps 1..64; 8 of
// 12) read smem; far positions (128/256/512/1024) read global (L2).
// Parallel-position formulation per warp (verified R8-R13); each of the 8
// warps processes 8 queries. fp16 output feeds GEMM2.
// ---------------------------------------------------------------------------
#define TBLK 64
#define WROWS 128
#define KVPAD 68   // floats per row (272B: float4-aligned, conflict-capped)
#define ATTN_SMEM (2 * WROWS * KVPAD * 4)   // 69632 B

__global__ __launch_bounds__(256)
void fenwick_attn_kernel(const float* __restrict__ qkv,
                         __half* __restrict__ outA)
{
    extern __shared__ float sm[];
    float* Kw = sm;                     // [WROWS][KVPAD]
    float* Vw = sm + WROWS * KVPAD;     // [WROWS][KVPAD]

    const int tid  = threadIdx.x;
    const int warp = tid >> 5;
    const int lane = tid & 31;
    const int t0 = blockIdx.x * TBLK;
    const int bh = blockIdx.y;
    const int b = bh >> 4;
    const int h = bh & 15;

    const float scale = 0.125f;
    const size_t rowStride = 3 * CH;
    const float* base = qkv + (size_t)b * SEQ * rowStride;
    const int w0 = t0 - 64;            // window start (global t of smem row 0)

    // Stage window: 128 rows x 64 floats (K and V), float4 granularity.
    // 2048 float4 slots per array; 256 threads x 8 iterations.
    #pragma unroll
    for (int k = 0; k < 8; k++) {
        int idx = k * 256 + tid;        // 0..2047
        int r  = idx >> 4;              // 0..127
        int c4 = idx & 15;              // float4 column
        int gt = w0 + r;
        if (gt >= 0) {
            const float* krow = base + (size_t)gt * rowStride + CH + h * DH;
            const float* vrow = base + (size_t)gt * rowStride + 2 * CH + h * DH;
            *(float4*)&Kw[r * KVPAD + c4 * 4] = *(const float4*)(krow + c4 * 4);
            *(float4*)&Vw[r * KVPAD + c4 * 4] = *(const float4*)(vrow + c4 * 4);
        }
    }
    __syncthreads();

    // Each warp handles 8 queries: t = t0 + warp*8 + i
    #pragma unroll 1
    for (int i = 0; i < 8; i++) {
        const int t = t0 + warp * 8 + i;

        bool active;
        int myPos;
        if (lane == 0) { myPos = t; active = true; }
        else           { int step = 1 << (lane - 1);
                         myPos = t - step;
                         active = (lane < 12) && (myPos >= 0); }
        if (!active) myPos = t;

        // Phase 1: per-lane dot product q[t] . K[myPos]
        float s = -CUDART_INF_F;
        const float4* qp4 = (const float4*)(base + (size_t)t * rowStride + h * DH);
        if (active && lane < 8) {
            // near: K from smem (row myPos - w0 guaranteed in [0, 128))
            const float* krow = &Kw[(myPos - w0) * KVPAD];
            float d = 0.0f;
            #pragma unroll
            for (int q = 0; q < 16; q++) {
                float4 qv = qp4[q];
                float4 kv = *(const float4*)(krow + q * 4);
                d += qv.x * kv.x + qv.y * kv.y + qv.z * kv.z + qv.w * kv.w;
            }
            s = d * scale;
        } else if (active) {
            // far: K from global
            const float4* kp4 = (const float4*)(base + (size_t)myPos * rowStride + CH + h * DH);
            float d = 0.0f;
            #pragma unroll
            for (int q = 0; q < 16; q++) {
                float4 qv = qp4[q];
                float4 kv = kp4[q];
                d += qv.x * kv.x + qv.y * kv.y + qv.z * kv.z + qv.w * kv.w;
            }
            s = d * scale;
        }

        // softmax over active lanes
        float m = s;
        #pragma unroll
        for (int off = 16; off; off >>= 1) m = fmaxf(m, __shfl_xor_sync(0xFFFFFFFFu, m, off));
        float e = active ? __expf(s - m) : 0.0f;
        float denom = e;
        #pragma unroll
        for (int off = 16; off; off >>= 1) denom += __shfl_xor_sync(0xFFFFFFFFu, denom, off);
        const float inv = 1.0f / denom;

        // Phase 2: V accumulate; near rows from smem, far from global.
        float o0 = 0.0f, o1 = 0.0f;
        #pragma unroll
        for (int j = 0; j < 8; j++) {
            float ej = __shfl_sync(0xFFFFFFFFu, e, j);
            int   pj = __shfl_sync(0xFFFFFFFFu, myPos, j);
            const float* vp = &Vw[(pj - w0) * KVPAD];   // ej==0 rows are still in-window (pj>=0 clamp -> row >= 0? )
            // guard: inactive lanes carry myPos=t (in window) so the read is safe
            o0 = fmaf(ej, vp[lane], o0);
            o1 = fmaf(ej, vp[lane + 32], o1);
        }
        #pragma unroll
        for (int j = 8; j < 12; j++) {
            float ej = __shfl_sync(0xFFFFFFFFu, e, j);
            int   pj = __shfl_sync(0xFFFFFFFFu, myPos, j);
            const float* vp = base + (size_t)pj * rowStride + 2 * CH + h * DH;
            o0 = fmaf(ej, vp[lane], o0);
            o1 = fmaf(ej, vp[lane + 32], o1);
        }
        o0 *= inv;
        o1 *= inv;

        const size_t o = ((size_t)b * SEQ + t) * CH + h * DH;
        outA[o + lane]      = __float2half_rn(o0);
        outA[o + lane + 32] = __float2half_rn(o1);
    }
}

// ---------------------------------------------------------------------------
// Launch
// ---------------------------------------------------------------------------
extern "C" void kernel_launch(void* const* d_in, const int* in_sizes, int n_in,
                              void* d_out, int out_size)
{
    const float* x      = (const float*)d_in[0];
    const float* W_qkv  = (const float*)d_in[1];
    const float* b_qkv  = (const float*)d_in[2];
    const float* W_proj = (const float*)d_in[3];
    const float* b_proj = (const float*)d_in[4];
    float* out = (float*)d_out;

    float *qkv;
    __half *A, *BQ, *BP;
    cudaGetSymbolAddress((void**)&qkv, g_qkv);
    cudaGetSymbolAddress((void**)&A,   g_A);
    cudaGetSymbolAddress((void**)&BQ,  g_BQ);
    cudaGetSymbolAddress((void**)&BP,  g_BP);

    cudaFuncSetAttribute(gemm_fp16_kernel,
                         cudaFuncAttributeMaxDynamicSharedMemorySize, GEMM_SMEM);
    cudaFuncSetAttribute(fenwick_attn_kernel,
                         cudaFuncAttributeMaxDynamicSharedMemorySize, ATTN_SMEM);

    conv_transpose_kernel<<<dim3(3 * CH / 32, CH / 32), 256>>>(W_qkv, BQ, CH, 3 * CH);
    conv_transpose_kernel<<<dim3(CH / 32, CH / 32), 256>>>(W_proj, BP, CH, CH);
    conv_fp16_kernel<<<(MROWS * CH / 4 + 255) / 256, 256>>>(x, A, MROWS * CH / 4);

    // GEMM1: [4096, 3072] = x @ W_qkv + b_qkv
    gemm_fp16_kernel<<<dim3(3 * CH / 128, MROWS / 128), 256, GEMM_SMEM>>>(
        A, BQ, b_qkv, qkv, 3 * CH, CH);

    // Attention with near-window smem tiling, fp16 output (overwrites A)
    fenwick_attn_kernel<<<dim3(SEQ / TBLK, BATCH * HEADS), 256, ATTN_SMEM>>>(qkv, A);

    // GEMM2: [4096, 1024] = att @ W_proj + b_proj
    gemm_fp16_kernel<<<dim3(CH / 128, MROWS / 128), 256, GEMM_SMEM>>>(
        A, BP, b_proj, out, CH, CH);
}

// round 15
// speedup vs baseline: 1.1793x; 1.1793x over previous
#include <cuda_runtime.h>
#include <cuda_fp16.h>
#include <math_constants.h>
#include <cstdint>

// Problem constants
#define BATCH 2
#define SEQ   2048
#define CH    1024
#define HEADS 16
#define DH    64
#define MROWS (BATCH*SEQ)   // 4096

// ---------------------------------------------------------------------------
// Device scratch
// ---------------------------------------------------------------------------
__device__ float  g_qkv[(size_t)MROWS * 3 * CH];
__device__ __half g_A[(size_t)MROWS * CH];
__device__ __half g_BQ[(size_t)(3*CH) * CH];   // W_qkv^T fp16
__device__ __half g_BP[(size_t)CH * CH];       // W_proj^T fp16

// ---------------------------------------------------------------------------
// Helpers
// ---------------------------------------------------------------------------
__device__ __forceinline__ uint32_t smem_u32(const void* p) {
    uint32_t a;
    asm("{ .reg .u64 t; cvta.to.shared.u64 t, %1; cvt.u32.u64 %0, t; }"
        : "=r"(a) : "l"(p));
    return a;
}

#define SWZ128(o) ((o) ^ (((o) >> 3) & 0x70))

#define CP_ASYNC16(dst_u32, src_ptr) \
    asm volatile("cp.async.cg.shared.global [%0], [%1], 16;\n" \
                 :: "r"(dst_u32), "l"(src_ptr))
#define CP_COMMIT() asm volatile("cp.async.commit_group;\n" ::: "memory")
#define CP_WAIT0()  asm volatile("cp.async.wait_group 0;\n" ::: "memory")
#define CP_WAIT1()  asm volatile("cp.async.wait_group 1;\n" ::: "memory")

#define LDSM_X4(r0, r1, r2, r3, addr) \
    asm volatile("ldmatrix.sync.aligned.m8n8.x4.shared.b16 {%0,%1,%2,%3}, [%4];" \
                 : "=r"(r0), "=r"(r1), "=r"(r2), "=r"(r3) : "r"(addr))
// fp16 MMA, f32 accumulate
#define MMA16816(d, a0, a1, a2, a3, b0, b1) \
    asm volatile("mma.sync.aligned.m16n8k16.row.col.f32.f16.f16.f32 " \
                 "{%0,%1,%2,%3},{%4,%5,%6,%7},{%8,%9},{%0,%1,%2,%3};" \
                 : "+f"((d)[0]), "+f"((d)[1]), "+f"((d)[2]), "+f"((d)[3]) \
                 : "r"(a0), "r"(a1), "r"(a2), "r"(a3), "r"(b0), "r"(b1))

// ---------------------------------------------------------------------------
// fp16 GEMM: C[M,N] = A[M,K] @ B[N,K]^T + bias
// CTA 256x128, KC=64, 2-stage double buffer, 8 warps in 4(M)x2(N) grid,
// 64x64 warp tiles (min smem traffic per FLOP: A-read x2, B-read x4).
// Stage: A 32KB | B 16KB = 48KB; 2 stages = 96KB; 1 CTA/SM.
// ---------------------------------------------------------------------------
#define KC 64
#define STAGE_BYTES 49152
#define GEMM_SMEM (1024 + 2 * STAGE_BYTES)   // 99328 B

__device__ __forceinline__ void load_chunk_tiles(
    const __half* __restrict__ A, const __half* __restrict__ B,
    int K, int m0, int n0, int c, uint32_t st, int tid)
{
    // A: 256 rows x 8 chunks of 16B = 2048 slots
    #pragma unroll
    for (int t = 0; t < 8; t++) {
        int idx = t * 256 + tid;
        int row = idx >> 3;
        int col = idx & 7;
        uint32_t off = SWZ128((uint32_t)(row * 128 + col * 16));
        size_t ga = (size_t)(m0 + row) * K + c * KC + col * 8;
        CP_ASYNC16(st + off, A + ga);
    }
    // B: 128 rows x 8 chunks = 1024 slots
    #pragma unroll
    for (int t = 0; t < 4; t++) {
        int idx = t * 256 + tid;
        int row = idx >> 3;
        int col = idx & 7;
        uint32_t off = SWZ128((uint32_t)(row * 128 + col * 16));
        size_t gb = (size_t)(n0 + row) * K + c * KC + col * 8;
        CP_ASYNC16(st + 32768 + off, B + gb);
    }
}

__global__ __launch_bounds__(256, 1)
void gemm_fp16_kernel(const __half* __restrict__ A,
                      const __half* __restrict__ B,
                      const float* __restrict__ bias,
                      float* __restrict__ C,
                      int N, int K)
{
    extern __shared__ char smem[];
    const uint32_t sb = smem_u32(smem);
    const uint32_t tiles = (sb + 1023) & ~1023u;
    const int tid  = threadIdx.x;
    const int wid  = tid >> 5;
    const int lane = tid & 31;
    const int m0 = blockIdx.y * 256;
    const int n0 = blockIdx.x * 128;
    const int NCHUNK = K / KC;

    const int warpM = wid >> 1;        // 0..3 -> 64-row band
    const int warpN = wid & 1;         // 0..1 -> 64-col band

    float acc[4][8][4];
    #pragma unroll
    for (int mt = 0; mt < 4; mt++)
        #pragma unroll
        for (int nt = 0; nt < 8; nt++)
            #pragma unroll
            for (int e = 0; e < 4; e++) acc[mt][nt][e] = 0.0f;

    // A ldmatrix.x4 (m16 x k16)
    const int aRowBase  = warpM * 64 + (lane & 15);
    const int aByteSel  = (lane >> 4) * 16;
    // B ldmatrix.x4 (two n8 tiles x k16) — layout verified R6-R14
    const int bRowSel   = warpN * 64 + (lane & 7) + ((lane >> 4) & 1) * 8;
    const int bByteSel  = ((lane >> 3) & 1) * 16;

    load_chunk_tiles(A, B, K, m0, n0, 0, tiles, tid);
    CP_COMMIT();

    for (int c = 0; c < NCHUNK; ++c) {
        if (c + 1 < NCHUNK) {
            load_chunk_tiles(A, B, K, m0, n0, c + 1,
                             tiles + ((c + 1) & 1) * STAGE_BYTES, tid);
            CP_COMMIT();
            CP_WAIT1();
        } else {
            CP_WAIT0();
        }
        __syncthreads();

        const uint32_t st = tiles + (c & 1) * STAGE_BYTES;
        const uint32_t aB = st;
        const uint32_t bB = st + 32768;

        #pragma unroll
        for (int kk = 0; kk < 4; kk++) {
            uint32_t fa[4][4], fb[4][4];
            #pragma unroll
            for (int mt = 0; mt < 4; mt++) {
                uint32_t aoff = SWZ128((uint32_t)((aRowBase + mt * 16) * 128 + kk * 32 + aByteSel));
                LDSM_X4(fa[mt][0], fa[mt][1], fa[mt][2], fa[mt][3], aB + aoff);
            }
            #pragma unroll
            for (int p = 0; p < 4; p++) {
                uint32_t boff = SWZ128((uint32_t)((bRowSel + p * 16) * 128 + kk * 32 + bByteSel));
                LDSM_X4(fb[p][0], fb[p][1], fb[p][2], fb[p][3], bB + boff);
            }
            #pragma unroll
            for (int mt = 0; mt < 4; mt++)
                #pragma unroll
                for (int nt = 0; nt < 8; nt++)
                    MMA16816(acc[mt][nt],
                             fa[mt][0], fa[mt][1], fa[mt][2], fa[mt][3],
                             fb[nt >> 1][(nt & 1) * 2], fb[nt >> 1][(nt & 1) * 2 + 1]);
        }
        __syncthreads();
    }

    // epilogue: bias + store
    #pragma unroll
    for (int mt = 0; mt < 4; mt++) {
        int r0 = m0 + warpM * 64 + mt * 16 + (lane >> 2);
        #pragma unroll
        for (int nt = 0; nt < 8; nt++) {
            int c0 = n0 + warpN * 64 + nt * 8 + (lane & 3) * 2;
            float2 bv = *(const float2*)(bias + c0);
            float2 o0 = make_float2(acc[mt][nt][0] + bv.x, acc[mt][nt][1] + bv.y);
            float2 o1 = make_float2(acc[mt][nt][2] + bv.x, acc[mt][nt][3] + bv.y);
            *(float2*)(C + (size_t)r0 * N + c0)       = o0;
            *(float2*)(C + (size_t)(r0 + 8) * N + c0) = o1;
        }
    }
}

// ---------------------------------------------------------------------------
// Convert fp32 -> fp16
// ---------------------------------------------------------------------------
__global__ __launch_bounds__(256)
void conv_fp16_kernel(const float* __restrict__ in,
                      __half* __restrict__ o, int n4)
{
    int i = blockIdx.x * 256 + threadIdx.x;
    if (i >= n4) return;
    float4 v = ((const float4*)in)[i];
    ((__half2*)o)[2 * i + 0] = __halves2half2(__float2half_rn(v.x), __float2half_rn(v.y));
    ((__half2*)o)[2 * i + 1] = __halves2half2(__float2half_rn(v.z), __float2half_rn(v.w));
}

// ---------------------------------------------------------------------------
// Transpose: W[K,N] fp32 -> Wt[N,K] fp16
// ---------------------------------------------------------------------------
__global__ __launch_bounds__(256)
void conv_transpose_kernel(const float* __restrict__ W,
                           __half* __restrict__ o, int K, int N)
{
    __shared__ float tile[32][33];
    const int n0 = blockIdx.x * 32;
    const int k0 = blockIdx.y * 32;
    const int tx = threadIdx.x & 31;
    const int ty = threadIdx.x >> 5;

    #pragma unroll
    for (int j = ty; j < 32; j += 8)
        tile[j][tx] = W[(size_t)(k0 + j) * N + n0 + tx];
    __syncthreads();

    #pragma unroll
    for (int j = ty; j < 32; j += 8)
        o[(size_t)(n0 + j) * K + k0 + tx] = __float2half_rn(tile[tx][j]);
}

// ---------------------------------------------------------------------------
// Fenwick sparse attention — R11 EXACT (verified fastest attention config).
// Parallel-position formulation; Q,K,V fp32; fp16 output feeds GEMM2.
// ---------------------------------------------------------------------------
__global__ __launch_bounds__(256)
void fenwick_attn_kernel(const float* __restrict__ qkv,
                         __half* __restrict__ outA)
{
    const int warp = threadIdx.x >> 5;
    const int lane = threadIdx.x & 31;
    const int t  = blockIdx.x * 8 + warp;
    const int bh = blockIdx.y;
    const int b = bh >> 4;
    const int h = bh & 15;

    const float scale = 0.125f;
    const size_t rowStride = 3 * CH;
    const float* base = qkv + (size_t)b * SEQ * rowStride;

    bool active;
    int myPos;
    if (lane == 0) { myPos = t; active = true; }
    else           { int step = 1 << (lane - 1);
                     myPos = t - step;
                     active = (lane < 12) && (myPos >= 0); }
    if (!active) myPos = t;

    float s = -CUDART_INF_F;
    if (active) {
        const float4* qp4 = (const float4*)(base + (size_t)t * rowStride + h * DH);
        const float4* kp4 = (const float4*)(base + (size_t)myPos * rowStride + CH + h * DH);
        float d = 0.0f;
        #pragma unroll
        for (int i = 0; i < 16; i++) {
            float4 qv = qp4[i];
            float4 kv = kp4[i];
            d += qv.x * kv.x + qv.y * kv.y + qv.z * kv.z + qv.w * kv.w;
        }
        s = d * scale;
    }

    float m = s;
    #pragma unroll
    for (int off = 16; off; off >>= 1) m = fmaxf(m, __shfl_xor_sync(0xFFFFFFFFu, m, off));
    float e = active ? __expf(s - m) : 0.0f;
    float denom = e;
    #pragma unroll
    for (int off = 16; off; off >>= 1) denom += __shfl_xor_sync(0xFFFFFFFFu, denom, off);
    const float inv = 1.0f / denom;

    float o0 = 0.0f, o1 = 0.0f;
    #pragma unroll
    for (int j = 0; j < 12; j++) {
        float ej = __shfl_sync(0xFFFFFFFFu, e, j);
        int   pj = __shfl_sync(0xFFFFFFFFu, myPos, j);
        const float* vp = base + (size_t)pj * rowStride + 2 * CH + h * DH;
        o0 = fmaf(ej, vp[lane], o0);
        o1 = fmaf(ej, vp[lane + 32], o1);
    }
    o0 *= inv;
    o1 *= inv;

    const size_t o = ((size_t)b * SEQ + t) * CH + h * DH;
    outA[o + lane]      = __float2half_rn(o0);
    outA[o + lane + 32] = __float2half_rn(o1);
}

// ---------------------------------------------------------------------------
// Launch
// ---------------------------------------------------------------------------
extern "C" void kernel_launch(void* const* d_in, const int* in_sizes, int n_in,
                              void* d_out, int out_size)
{
    const float* x      = (const float*)d_in[0];
    const float* W_qkv  = (const float*)d_in[1];
    const float* b_qkv  = (const float*)d_in[2];
    const float* W_proj = (const float*)d_in[3];
    const float* b_proj = (const float*)d_in[4];
    float* out = (float*)d_out;

    float *qkv;
    __half *A, *BQ, *BP;
    cudaGetSymbolAddress((void**)&qkv, g_qkv);
    cudaGetSymbolAddress((void**)&A,   g_A);
    cudaGetSymbolAddress((void**)&BQ,  g_BQ);
    cudaGetSymbolAddress((void**)&BP,  g_BP);

    cudaFuncSetAttribute(gemm_fp16_kernel,
                         cudaFuncAttributeMaxDynamicSharedMemorySize, GEMM_SMEM);

    conv_transpose_kernel<<<dim3(3 * CH / 32, CH / 32), 256>>>(W_qkv, BQ, CH, 3 * CH);
    conv_transpose_kernel<<<dim3(CH / 32, CH / 32), 256>>>(W_proj, BP, CH, CH);
    conv_fp16_kernel<<<(MROWS * CH / 4 + 255) / 256, 256>>>(x, A, MROWS * CH / 4);

    // GEMM1: [4096, 3072] = x @ W_qkv + b_qkv   (CTA 256x128, grid 24x16)
    gemm_fp16_kernel<<<dim3(3 * CH / 128, MROWS / 256), 256, GEMM_SMEM>>>(
        A, BQ, b_qkv, qkv, 3 * CH, CH);

    // Attention (R11 exact), fp16 output (overwrites A)
    fenwick_attn_kernel<<<dim3(SEQ / 8, BATCH * HEADS), 256>>>(qkv, A);

    // GEMM2: [4096, 1024] = att @ W_proj + b_proj  (grid 8x16)
    gemm_fp16_kernel<<<dim3(CH / 128, MROWS / 256), 256, GEMM_SMEM>>>(
        A, BP, b_proj, out, CH, CH);
}

// round 16
// speedup vs baseline: 1.3703x; 1.1619x over previous
#include <cuda_runtime.h>
#include <cuda_fp16.h>
#include <math_constants.h>
#include <cstdint>

// Problem constants
#define BATCH 2
#define SEQ   2048
#define CH    1024
#define HEADS 16
#define DH    64
#define MROWS (BATCH*SEQ)   // 4096

// ---------------------------------------------------------------------------
// Device scratch
// ---------------------------------------------------------------------------
__device__ float  g_qkv[(size_t)MROWS * 3 * CH];
__device__ __half g_A[(size_t)MROWS * CH];
__device__ __half g_BQ[(size_t)(3*CH) * CH];   // W_qkv^T fp16
__device__ __half g_BP[(size_t)CH * CH];       // W_proj^T fp16

// ---------------------------------------------------------------------------
// Helpers
// ---------------------------------------------------------------------------
__device__ __forceinline__ uint32_t smem_u32(const void* p) {
    uint32_t a;
    asm("{ .reg .u64 t; cvta.to.shared.u64 t, %1; cvt.u32.u64 %0, t; }"
        : "=r"(a) : "l"(p));
    return a;
}

#define SWZ128(o) ((o) ^ (((o) >> 3) & 0x70))

#define CP_ASYNC16(dst_u32, src_ptr) \
    asm volatile("cp.async.cg.shared.global [%0], [%1], 16;\n" \
                 :: "r"(dst_u32), "l"(src_ptr))
#define CP_COMMIT() asm volatile("cp.async.commit_group;\n" ::: "memory")
#define CP_WAIT0()  asm volatile("cp.async.wait_group 0;\n" ::: "memory")
#define CP_WAIT1()  asm volatile("cp.async.wait_group 1;\n" ::: "memory")

#define LDSM_X4(r0, r1, r2, r3, addr) \
    asm volatile("ldmatrix.sync.aligned.m8n8.x4.shared.b16 {%0,%1,%2,%3}, [%4];" \
                 : "=r"(r0), "=r"(r1), "=r"(r2), "=r"(r3) : "r"(addr))
// fp16 MMA, f32 accumulate
#define MMA16816(d, a0, a1, a2, a3, b0, b1) \
    asm volatile("mma.sync.aligned.m16n8k16.row.col.f32.f16.f16.f32 " \
                 "{%0,%1,%2,%3},{%4,%5,%6,%7},{%8,%9},{%0,%1,%2,%3};" \
                 : "+f"((d)[0]), "+f"((d)[1]), "+f"((d)[2]), "+f"((d)[3]) \
                 : "r"(a0), "r"(a1), "r"(a2), "r"(a3), "r"(b0), "r"(b1))

// ---------------------------------------------------------------------------
// fp16 GEMM: C[M,N] = A[M,K] @ B[N,K]^T + bias
// R11 EXACT (fastest measured, frozen): CTA 128x128, KC=64, 2-stage double
// buffer, TWO CTAs PER SM, 8 warps 2(M)x4(N), 64x32 warp tiles.
// ---------------------------------------------------------------------------
#define KC 64
#define STAGE_BYTES 32768
#define GEMM_SMEM (1024 + 2 * STAGE_BYTES)   // 66560 B

__device__ __forceinline__ void load_chunk_tiles(
    const __half* __restrict__ A, const __half* __restrict__ B,
    int K, int m0, int n0, int c, uint32_t st, int tid)
{
    #pragma unroll
    for (int t = 0; t < 4; t++) {
        int idx = t * 256 + tid;     // 0..1023
        int row = idx >> 3;          // 0..127
        int col = idx & 7;           // 16B chunk
        uint32_t off = SWZ128(row * 128 + col * 16);
        size_t ga = (size_t)(m0 + row) * K + c * KC + col * 8;
        size_t gb = (size_t)(n0 + row) * K + c * KC + col * 8;
        CP_ASYNC16(st + off,         A + ga);
        CP_ASYNC16(st + 16384 + off, B + gb);
    }
}

__global__ __launch_bounds__(256, 2)
void gemm_fp16_kernel(const __half* __restrict__ A,
                      const __half* __restrict__ B,
                      const float* __restrict__ bias,
                      float* __restrict__ C,
                      int N, int K)
{
    extern __shared__ char smem[];
    const uint32_t sb = smem_u32(smem);
    const uint32_t tiles = (sb + 1023) & ~1023u;
    const int tid  = threadIdx.x;
    const int wid  = tid >> 5;
    const int lane = tid & 31;
    const int m0 = blockIdx.y * 128;
    const int n0 = blockIdx.x * 128;
    const int NCHUNK = K / KC;

    const int warpM = wid >> 2;        // 0..1
    const int warpN = wid & 3;         // 0..3

    float acc[4][4][4];
    #pragma unroll
    for (int mt = 0; mt < 4; mt++)
        #pragma unroll
        for (int nt = 0; nt < 4; nt++)
            #pragma unroll
            for (int e = 0; e < 4; e++) acc[mt][nt][e] = 0.0f;

    // A ldmatrix.x4 (m16 x k16)
    const int aRowBase  = warpM * 64 + (lane & 15);
    const int aByteSel  = (lane >> 4) * 16;
    // B ldmatrix.x4 (two n8 tiles x k16) — layout verified R6-R15
    const int bRowSel   = warpN * 32 + (lane & 7) + ((lane >> 4) & 1) * 8;
    const int bByteSel  = ((lane >> 3) & 1) * 16;

    load_chunk_tiles(A, B, K, m0, n0, 0, tiles, tid);
    CP_COMMIT();

    for (int c = 0; c < NCHUNK; ++c) {
        if (c + 1 < NCHUNK) {
            load_chunk_tiles(A, B, K, m0, n0, c + 1,
                             tiles + ((c + 1) & 1) * STAGE_BYTES, tid);
            CP_COMMIT();
            CP_WAIT1();
        } else {
            CP_WAIT0();
        }
        __syncthreads();

        const uint32_t st = tiles + (c & 1) * STAGE_BYTES;
        const uint32_t aB = st;
        const uint32_t bB = st + 16384;

        #pragma unroll
        for (int kk = 0; kk < 4; kk++) {
            uint32_t fa[4][4], fb[2][4];
            #pragma unroll
            for (int mt = 0; mt < 4; mt++) {
                uint32_t aoff = SWZ128((uint32_t)((aRowBase + mt * 16) * 128 + kk * 32 + aByteSel));
                LDSM_X4(fa[mt][0], fa[mt][1], fa[mt][2], fa[mt][3], aB + aoff);
            }
            #pragma unroll
            for (int p = 0; p < 2; p++) {
                uint32_t boff = SWZ128((uint32_t)((bRowSel + p * 16) * 128 + kk * 32 + bByteSel));
                LDSM_X4(fb[p][0], fb[p][1], fb[p][2], fb[p][3], bB + boff);
            }
            #pragma unroll
            for (int mt = 0; mt < 4; mt++)
                #pragma unroll
                for (int nt = 0; nt < 4; nt++)
                    MMA16816(acc[mt][nt],
                             fa[mt][0], fa[mt][1], fa[mt][2], fa[mt][3],
                             fb[nt >> 1][(nt & 1) * 2], fb[nt >> 1][(nt & 1) * 2 + 1]);
        }
        __syncthreads();
    }

    // epilogue: bias + store
    #pragma unroll
    for (int mt = 0; mt < 4; mt++) {
        int r0 = m0 + warpM * 64 + mt * 16 + (lane >> 2);
        #pragma unroll
        for (int nt = 0; nt < 4; nt++) {
            int c0 = n0 + warpN * 32 + nt * 8 + (lane & 3) * 2;
            float2 bv = *(const float2*)(bias + c0);
            float2 o0 = make_float2(acc[mt][nt][0] + bv.x, acc[mt][nt][1] + bv.y);
            float2 o1 = make_float2(acc[mt][nt][2] + bv.x, acc[mt][nt][3] + bv.y);
            *(float2*)(C + (size_t)r0 * N + c0)       = o0;
            *(float2*)(C + (size_t)(r0 + 8) * N + c0) = o1;
        }
    }
}

// ---------------------------------------------------------------------------
// Convert fp32 -> fp16
// ---------------------------------------------------------------------------
__global__ __launch_bounds__(256)
void conv_fp16_kernel(const float* __restrict__ in,
                      __half* __restrict__ o, int n4)
{
    int i = blockIdx.x * 256 + threadIdx.x;
    if (i >= n4) return;
    float4 v = ((const float4*)in)[i];
    ((__half2*)o)[2 * i + 0] = __halves2half2(__float2half_rn(v.x), __float2half_rn(v.y));
    ((__half2*)o)[2 * i + 1] = __halves2half2(__float2half_rn(v.z), __float2half_rn(v.w));
}

// ---------------------------------------------------------------------------
// Transpose: W[K,N] fp32 -> Wt[N,K] fp16
// ---------------------------------------------------------------------------
__global__ __launch_bounds__(256)
void conv_transpose_kernel(const float* __restrict__ W,
                           __half* __restrict__ o, int K, int N)
{
    __shared__ float tile[32][33];
    const int n0 = blockIdx.x * 32;
    const int k0 = blockIdx.y * 32;
    const int tx = threadIdx.x & 31;
    const int ty = threadIdx.x >> 5;

    #pragma unroll
    for (int j = ty; j < 32; j += 8)
        tile[j][tx] = W[(size_t)(k0 + j) * N + n0 + tx];
    __syncthreads();

    #pragma unroll
    for (int j = ty; j < 32; j += 8)
        o[(size_t)(n0 + j) * K + k0 + tx] = __float2half_rn(tile[tx][j]);
}

// ---------------------------------------------------------------------------
// Fenwick sparse attention — coalesced formulation.
// All 12 positions are uniform per warp (derived from t). Each lane owns
// dims {lane, lane+32}. Per position: coalesced K row read -> per-lane
// partial. Then 12 BATCHED butterfly reductions (independent SHFLs),
// softmax fully in registers (every lane has all 12 scores), and a
// shuffle-free coalesced V accumulate. fp16 output feeds GEMM2.
// ---------------------------------------------------------------------------
__global__ __launch_bounds__(256)
void fenwick_attn_kernel(const float* __restrict__ qkv,
                         __half* __restrict__ outA)
{
    const int warp = threadIdx.x >> 5;
    const int lane = threadIdx.x & 31;
    const int t  = blockIdx.x * 8 + warp;
    const int bh = blockIdx.y;
    const int b = bh >> 4;
    const int h = bh & 15;

    const float scale = 0.125f;   // 64^-0.5
    const size_t rowStride = 3 * CH;
    const float* base = qkv + (size_t)b * SEQ * rowStride;

    // query dims owned by this lane
    const float* qp = base + (size_t)t * rowStride + h * DH;
    const float q0 = qp[lane];
    const float q1 = qp[lane + 32];

    // positions (uniform per warp): j=0 -> t (diag); j>=1 -> t - 2^(j-1)
    int  pos[12];
    bool valid[12];
    pos[0] = t; valid[0] = true;
    #pragma unroll
    for (int j = 1; j < 12; j++) {
        int p = t - (1 << (j - 1));
        valid[j] = (p >= 0);
        pos[j] = valid[j] ? p : t;    // safe address; e will be zeroed
    }

    // Phase 1: coalesced per-lane partials for all 12 positions (MLP ~24)
    float part[12];
    #pragma unroll
    for (int j = 0; j < 12; j++) {
        const float* kp = base + (size_t)pos[j] * rowStride + CH + h * DH;
        part[j] = q0 * kp[lane] + q1 * kp[lane + 32];
    }

    // 12 batched butterfly reductions (independent -> pipelined)
    #pragma unroll
    for (int off = 16; off; off >>= 1) {
        #pragma unroll
        for (int j = 0; j < 12; j++)
            part[j] += __shfl_xor_sync(0xFFFFFFFFu, part[j], off);
    }

    // softmax in registers (identical on every lane)
    float s[12];
    #pragma unroll
    for (int j = 0; j < 12; j++) s[j] = part[j] * scale;
    float m = s[0];
    #pragma unroll
    for (int j = 1; j < 12; j++) if (valid[j]) m = fmaxf(m, s[j]);
    float e[12];
    float denom = 0.0f;
    #pragma unroll
    for (int j = 0; j < 12; j++) {
        e[j] = valid[j] ? __expf(s[j] - m) : 0.0f;
        denom += e[j];
    }
    const float inv = 1.0f / denom;

    // Phase 2: coalesced V accumulate, zero shuffles
    float o0 = 0.0f, o1 = 0.0f;
    #pragma unroll
    for (int j = 0; j < 12; j++) {
        const float* vp = base + (size_t)pos[j] * rowStride + 2 * CH + h * DH;
        o0 = fmaf(e[j], vp[lane], o0);
        o1 = fmaf(e[j], vp[lane + 32], o1);
    }
    o0 *= inv;
    o1 *= inv;

    const size_t o = ((size_t)b * SEQ + t) * CH + h * DH;
    outA[o + lane]      = __float2half_rn(o0);
    outA[o + lane + 32] = __float2half_rn(o1);
}

// ---------------------------------------------------------------------------
// Launch
// ---------------------------------------------------------------------------
extern "C" void kernel_launch(void* const* d_in, const int* in_sizes, int n_in,
                              void* d_out, int out_size)
{
    const float* x      = (const float*)d_in[0];
    const float* W_qkv  = (const float*)d_in[1];
    const float* b_qkv  = (const float*)d_in[2];
    const float* W_proj = (const float*)d_in[3];
    const float* b_proj = (const float*)d_in[4];
    float* out = (float*)d_out;

    float *qkv;
    __half *A, *BQ, *BP;
    cudaGetSymbolAddress((void**)&qkv, g_qkv);
    cudaGetSymbolAddress((void**)&A,   g_A);
    cudaGetSymbolAddress((void**)&BQ,  g_BQ);
    cudaGetSymbolAddress((void**)&BP,  g_BP);

    cudaFuncSetAttribute(gemm_fp16_kernel,
                         cudaFuncAttributeMaxDynamicSharedMemorySize, GEMM_SMEM);

    conv_transpose_kernel<<<dim3(3 * CH / 32, CH / 32), 256>>>(W_qkv, BQ, CH, 3 * CH);
    conv_transpose_kernel<<<dim3(CH / 32, CH / 32), 256>>>(W_proj, BP, CH, CH);
    conv_fp16_kernel<<<(MROWS * CH / 4 + 255) / 256, 256>>>(x, A, MROWS * CH / 4);

    // GEMM1: [4096, 3072] = x @ W_qkv + b_qkv
    gemm_fp16_kernel<<<dim3(3 * CH / 128, MROWS / 128), 256, GEMM_SMEM>>>(
        A, BQ, b_qkv, qkv, 3 * CH, CH);

    // Attention (coalesced formulation), fp16 output (overwrites A)
    fenwick_attn_kernel<<<dim3(SEQ / 8, BATCH * HEADS), 256>>>(qkv, A);

    // GEMM2: [4096, 1024] = att @ W_proj + b_proj
    gemm_fp16_kernel<<<dim3(CH / 128, MROWS / 128), 256, GEMM_SMEM>>>(
        A, BP, b_proj, out, CH, CH);
}

// round 17
// speedup vs baseline: 1.4467x; 1.0558x over previous
#include <cuda_runtime.h>
#include <cuda_fp16.h>
#include <math_constants.h>
#include <cstdint>

// Problem constants
#define BATCH 2
#define SEQ   2048
#define CH    1024
#define HEADS 16
#define DH    64
#define MROWS (BATCH*SEQ)   // 4096

// ---------------------------------------------------------------------------
// Device scratch
// ---------------------------------------------------------------------------
__device__ float  g_q[(size_t)MROWS * CH];          // Q fp32 (attention)
__device__ __half g_kv[(size_t)MROWS * 2 * CH];     // K,V fp16 (attention)
__device__ __half g_A[(size_t)MROWS * CH];
__device__ __half g_BQ[(size_t)(3*CH) * CH];        // W_qkv^T fp16
__device__ __half g_BP[(size_t)CH * CH];            // W_proj^T fp16

// ---------------------------------------------------------------------------
// Helpers
// ---------------------------------------------------------------------------
__device__ __forceinline__ uint32_t smem_u32(const void* p) {
    uint32_t a;
    asm("{ .reg .u64 t; cvta.to.shared.u64 t, %1; cvt.u32.u64 %0, t; }"
        : "=r"(a) : "l"(p));
    return a;
}

#define SWZ128(o) ((o) ^ (((o) >> 3) & 0x70))

#define CP_ASYNC16(dst_u32, src_ptr) \
    asm volatile("cp.async.cg.shared.global [%0], [%1], 16;\n" \
                 :: "r"(dst_u32), "l"(src_ptr))
#define CP_COMMIT() asm volatile("cp.async.commit_group;\n" ::: "memory")
#define CP_WAIT0()  asm volatile("cp.async.wait_group 0;\n" ::: "memory")
#define CP_WAIT1()  asm volatile("cp.async.wait_group 1;\n" ::: "memory")

#define LDSM_X4(r0, r1, r2, r3, addr) \
    asm volatile("ldmatrix.sync.aligned.m8n8.x4.shared.b16 {%0,%1,%2,%3}, [%4];" \
                 : "=r"(r0), "=r"(r1), "=r"(r2), "=r"(r3) : "r"(addr))
// fp16 MMA, f32 accumulate
#define MMA16816(d, a0, a1, a2, a3, b0, b1) \
    asm volatile("mma.sync.aligned.m16n8k16.row.col.f32.f16.f16.f32 " \
                 "{%0,%1,%2,%3},{%4,%5,%6,%7},{%8,%9},{%0,%1,%2,%3};" \
                 : "+f"((d)[0]), "+f"((d)[1]), "+f"((d)[2]), "+f"((d)[3]) \
                 : "r"(a0), "r"(a1), "r"(a2), "r"(a3), "r"(b0), "r"(b1))

// ---------------------------------------------------------------------------
// fp16 GEMM with split epilogue:
//   columns <  qN : fp32 store into Cq (row stride qN)
//   columns >= qN : fp16 store into KVh (row stride N - qN), NO fp32 copy
// The qN boundary is 128-aligned so each CTA takes exactly one path (uniform).
// Mainloop is R11 EXACT (frozen): CTA 128x128, KC=64, 2-stage, 2 CTAs/SM,
// 8 warps 2(M)x4(N), 64x32 warp tiles.
// ---------------------------------------------------------------------------
#define KC 64
#define STAGE_BYTES 32768
#define GEMM_SMEM (1024 + 2 * STAGE_BYTES)   // 66560 B

__device__ __forceinline__ void load_chunk_tiles(
    const __half* __restrict__ A, const __half* __restrict__ B,
    int K, int m0, int n0, int c, uint32_t st, int tid)
{
    #pragma unroll
    for (int t = 0; t < 4; t++) {
        int idx = t * 256 + tid;     // 0..1023
        int row = idx >> 3;          // 0..127
        int col = idx & 7;           // 16B chunk
        uint32_t off = SWZ128(row * 128 + col * 16);
        size_t ga = (size_t)(m0 + row) * K + c * KC + col * 8;
        size_t gb = (size_t)(n0 + row) * K + c * KC + col * 8;
        CP_ASYNC16(st + off,         A + ga);
        CP_ASYNC16(st + 16384 + off, B + gb);
    }
}

__global__ __launch_bounds__(256, 2)
void gemm_fp16_kernel(const __half* __restrict__ A,
                      const __half* __restrict__ B,
                      const float* __restrict__ bias,
                      float* __restrict__ Cq,
                      int qN,
                      __half* __restrict__ KVh,
                      int N, int K)
{
    extern __shared__ char smem[];
    const uint32_t sb = smem_u32(smem);
    const uint32_t tiles = (sb + 1023) & ~1023u;
    const int tid  = threadIdx.x;
    const int wid  = tid >> 5;
    const int lane = tid & 31;
    const int m0 = blockIdx.y * 128;
    const int n0 = blockIdx.x * 128;
    const int NCHUNK = K / KC;

    const int warpM = wid >> 2;        // 0..1
    const int warpN = wid & 3;         // 0..3

    float acc[4][4][4];
    #pragma unroll
    for (int mt = 0; mt < 4; mt++)
        #pragma unroll
        for (int nt = 0; nt < 4; nt++)
            #pragma unroll
            for (int e = 0; e < 4; e++) acc[mt][nt][e] = 0.0f;

    // A ldmatrix.x4 (m16 x k16)
    const int aRowBase  = warpM * 64 + (lane & 15);
    const int aByteSel  = (lane >> 4) * 16;
    // B ldmatrix.x4 (two n8 tiles x k16) — layout verified R6-R16
    const int bRowSel   = warpN * 32 + (lane & 7) + ((lane >> 4) & 1) * 8;
    const int bByteSel  = ((lane >> 3) & 1) * 16;

    load_chunk_tiles(A, B, K, m0, n0, 0, tiles, tid);
    CP_COMMIT();

    for (int c = 0; c < NCHUNK; ++c) {
        if (c + 1 < NCHUNK) {
            load_chunk_tiles(A, B, K, m0, n0, c + 1,
                             tiles + ((c + 1) & 1) * STAGE_BYTES, tid);
            CP_COMMIT();
            CP_WAIT1();
        } else {
            CP_WAIT0();
        }
        __syncthreads();

        const uint32_t st = tiles + (c & 1) * STAGE_BYTES;
        const uint32_t aB = st;
        const uint32_t bB = st + 16384;

        #pragma unroll
        for (int kk = 0; kk < 4; kk++) {
            uint32_t fa[4][4], fb[2][4];
            #pragma unroll
            for (int mt = 0; mt < 4; mt++) {
                uint32_t aoff = SWZ128((uint32_t)((aRowBase + mt * 16) * 128 + kk * 32 + aByteSel));
                LDSM_X4(fa[mt][0], fa[mt][1], fa[mt][2], fa[mt][3], aB + aoff);
            }
            #pragma unroll
            for (int p = 0; p < 2; p++) {
                uint32_t boff = SWZ128((uint32_t)((bRowSel + p * 16) * 128 + kk * 32 + bByteSel));
                LDSM_X4(fb[p][0], fb[p][1], fb[p][2], fb[p][3], bB + boff);
            }
            #pragma unroll
            for (int mt = 0; mt < 4; mt++)
                #pragma unroll
                for (int nt = 0; nt < 4; nt++)
                    MMA16816(acc[mt][nt],
                             fa[mt][0], fa[mt][1], fa[mt][2], fa[mt][3],
                             fb[nt >> 1][(nt & 1) * 2], fb[nt >> 1][(nt & 1) * 2 + 1]);
        }
        __syncthreads();
    }

    // epilogue: bias + split store (uniform per CTA: n0 either < qN or >= qN)
    if (n0 < qN) {
        // fp32 path (Q region / GEMM2 output), row stride qN
        #pragma unroll
        for (int mt = 0; mt < 4; mt++) {
            int r0 = m0 + warpM * 64 + mt * 16 + (lane >> 2);
            #pragma unroll
            for (int nt = 0; nt < 4; nt++) {
                int c0 = n0 + warpN * 32 + nt * 8 + (lane & 3) * 2;
                float2 bv = *(const float2*)(bias + c0);
                float2 o0 = make_float2(acc[mt][nt][0] + bv.x, acc[mt][nt][1] + bv.y);
                float2 o1 = make_float2(acc[mt][nt][2] + bv.x, acc[mt][nt][3] + bv.y);
                *(float2*)(Cq + (size_t)r0 * qN + c0)       = o0;
                *(float2*)(Cq + (size_t)(r0 + 8) * qN + c0) = o1;
            }
        }
    } else {
        // fp16 path (K/V region), row stride N - qN
        const int kvN = N - qN;
        #pragma unroll
        for (int mt = 0; mt < 4; mt++) {
            int r0 = m0 + warpM * 64 + mt * 16 + (lane >> 2);
            #pragma unroll
            for (int nt = 0; nt < 4; nt++) {
                int c0 = n0 + warpN * 32 + nt * 8 + (lane & 3) * 2;
                float2 bv = *(const float2*)(bias + c0);
                int cv = c0 - qN;
                *(__half2*)(KVh + (size_t)r0 * kvN + cv) =
                    __halves2half2(__float2half_rn(acc[mt][nt][0] + bv.x),
                                   __float2half_rn(acc[mt][nt][1] + bv.y));
                *(__half2*)(KVh + (size_t)(r0 + 8) * kvN + cv) =
                    __halves2half2(__float2half_rn(acc[mt][nt][2] + bv.x),
                                   __float2half_rn(acc[mt][nt][3] + bv.y));
            }
        }
    }
}

// ---------------------------------------------------------------------------
// Convert fp32 -> fp16
// ---------------------------------------------------------------------------
__global__ __launch_bounds__(256)
void conv_fp16_kernel(const float* __restrict__ in,
                      __half* __restrict__ o, int n4)
{
    int i = blockIdx.x * 256 + threadIdx.x;
    if (i >= n4) return;
    float4 v = ((const float4*)in)[i];
    ((__half2*)o)[2 * i + 0] = __halves2half2(__float2half_rn(v.x), __float2half_rn(v.y));
    ((__half2*)o)[2 * i + 1] = __halves2half2(__float2half_rn(v.z), __float2half_rn(v.w));
}

// ---------------------------------------------------------------------------
// Transpose: W[K,N] fp32 -> Wt[N,K] fp16
// ---------------------------------------------------------------------------
__global__ __launch_bounds__(256)
void conv_transpose_kernel(const float* __restrict__ W,
                           __half* __restrict__ o, int K, int N)
{
    __shared__ float tile[32][33];
    const int n0 = blockIdx.x * 32;
    const int k0 = blockIdx.y * 32;
    const int tx = threadIdx.x & 31;
    const int ty = threadIdx.x >> 5;

    #pragma unroll
    for (int j = ty; j < 32; j += 8)
        tile[j][tx] = W[(size_t)(k0 + j) * N + n0 + tx];
    __syncthreads();

    #pragma unroll
    for (int j = ty; j < 32; j += 8)
        o[(size_t)(n0 + j) * K + k0 + tx] = __float2half_rn(tile[tx][j]);
}

// ---------------------------------------------------------------------------
// Fenwick sparse attention — coalesced formulation (R16 verified) with
// fp16 K/V. Lane owns dims {2*lane, 2*lane+1}. Per position one __half2
// coalesced load per K row (half the R16 wavefronts). Q stays fp32.
// Batched butterfly reductions; softmax in registers; shuffle-free V pass.
// fp16 output feeds GEMM2.
// ---------------------------------------------------------------------------
__global__ __launch_bounds__(256)
void fenwick_attn_kernel(const float* __restrict__ qbuf,
                         const __half* __restrict__ kv,
                         __half* __restrict__ outA)
{
    const int warp = threadIdx.x >> 5;
    const int lane = threadIdx.x & 31;
    const int t  = blockIdx.x * 8 + warp;
    const int bh = blockIdx.y;
    const int b = bh >> 4;
    const int h = bh & 15;

    const float scale = 0.125f;   // 64^-0.5
    const float* qbase = qbuf + (size_t)b * SEQ * CH;
    const __half* kvbase = kv + (size_t)b * SEQ * (2 * CH);

    // query dims owned by this lane: {2*lane, 2*lane+1}
    const float2 qv = *(const float2*)(qbase + (size_t)t * CH + h * DH + 2 * lane);

    // positions (uniform per warp)
    int  pos[12];
    bool valid[12];
    pos[0] = t; valid[0] = true;
    #pragma unroll
    for (int j = 1; j < 12; j++) {
        int p = t - (1 << (j - 1));
        valid[j] = (p >= 0);
        pos[j] = valid[j] ? p : t;
    }

    // Phase 1: coalesced per-lane partials (one half2 load per K row)
    float part[12];
    #pragma unroll
    for (int j = 0; j < 12; j++) {
        const __half2 kh = *(const __half2*)(kvbase + (size_t)pos[j] * (2 * CH) + h * DH + 2 * lane);
        float2 kf = __half22float2(kh);
        part[j] = qv.x * kf.x + qv.y * kf.y;
    }

    // 12 batched butterfly reductions
    #pragma unroll
    for (int off = 16; off; off >>= 1) {
        #pragma unroll
        for (int j = 0; j < 12; j++)
            part[j] += __shfl_xor_sync(0xFFFFFFFFu, part[j], off);
    }

    // softmax in registers
    float m = part[0] * scale;
    float s[12];
    s[0] = part[0] * scale;
    #pragma unroll
    for (int j = 1; j < 12; j++) {
        s[j] = part[j] * scale;
        if (valid[j]) m = fmaxf(m, s[j]);
    }
    float e[12];
    float denom = 0.0f;
    #pragma unroll
    for (int j = 0; j < 12; j++) {
        e[j] = valid[j] ? __expf(s[j] - m) : 0.0f;
        denom += e[j];
    }
    const float inv = 1.0f / denom;

    // Phase 2: coalesced fp16 V accumulate (one half2 load per row)
    float o0 = 0.0f, o1 = 0.0f;
    #pragma unroll
    for (int j = 0; j < 12; j++) {
        const __half2 vh = *(const __half2*)(kvbase + (size_t)pos[j] * (2 * CH) + CH + h * DH + 2 * lane);
        float2 vf = __half22float2(vh);
        o0 = fmaf(e[j], vf.x, o0);
        o1 = fmaf(e[j], vf.y, o1);
    }
    o0 *= inv;
    o1 *= inv;

    // output dims {2*lane, 2*lane+1} -> coalesced half2 store
    const size_t o = ((size_t)b * SEQ + t) * CH + h * DH;
    *(__half2*)(outA + o + 2 * lane) =
        __halves2half2(__float2half_rn(o0), __float2half_rn(o1));
}

// ---------------------------------------------------------------------------
// Launch
// ---------------------------------------------------------------------------
extern "C" void kernel_launch(void* const* d_in, const int* in_sizes, int n_in,
                              void* d_out, int out_size)
{
    const float* x      = (const float*)d_in[0];
    const float* W_qkv  = (const float*)d_in[1];
    const float* b_qkv  = (const float*)d_in[2];
    const float* W_proj = (const float*)d_in[3];
    const float* b_proj = (const float*)d_in[4];
    float* out = (float*)d_out;

    float *q;
    __half *kvp, *A, *BQ, *BP;
    cudaGetSymbolAddress((void**)&q,   g_q);
    cudaGetSymbolAddress((void**)&kvp, g_kv);
    cudaGetSymbolAddress((void**)&A,   g_A);
    cudaGetSymbolAddress((void**)&BQ,  g_BQ);
    cudaGetSymbolAddress((void**)&BP,  g_BP);

    cudaFuncSetAttribute(gemm_fp16_kernel,
                         cudaFuncAttributeMaxDynamicSharedMemorySize, GEMM_SMEM);

    conv_transpose_kernel<<<dim3(3 * CH / 32, CH / 32), 256>>>(W_qkv, BQ, CH, 3 * CH);
    conv_transpose_kernel<<<dim3(CH / 32, CH / 32), 256>>>(W_proj, BP, CH, CH);
    conv_fp16_kernel<<<(MROWS * CH / 4 + 255) / 256, 256>>>(x, A, MROWS * CH / 4);

    // GEMM1: [4096, 3072] = x @ W_qkv + b_qkv
    //   cols [0, 1024)   -> Q fp32
    //   cols [1024, 3072) -> K,V fp16 (no fp32 copy)
    gemm_fp16_kernel<<<dim3(3 * CH / 128, MROWS / 128), 256, GEMM_SMEM>>>(
        A, BQ, b_qkv, q, CH, kvp, 3 * CH, CH);

    // Attention (Q fp32, K/V fp16, coalesced half2), fp16 output (overwrites A)
    fenwick_attn_kernel<<<dim3(SEQ / 8, BATCH * HEADS), 256>>>(q, kvp, A);

    // GEMM2: [4096, 1024] = att @ W_proj + b_proj (all columns fp32 -> out)
    gemm_fp16_kernel<<<dim3(CH / 128, MROWS / 128), 256, GEMM_SMEM>>>(
        A, BP, b_proj, out, CH, (__half*)nullptr, CH, CH);
}